// round 6
// baseline (speedup 1.0000x reference)
#include <cuda_runtime.h>
#include <cuda_bf16.h>

#define BATCH 8
#define FDIM 16
#define NPTS 2048
#define TILE 128
#define NTILE (NPTS / TILE)             // 16
#define NOFF  (NTILE * (NTILE - 1) / 2) // 120 off-diagonal tiles
#define NTRI  (NOFF + NTILE)            // 136 total

// Dynamic smem layout (bytes)
#define SM_AS    0                       // 16x128 f32 = 8KB
#define SM_BS    8192                    // 8KB
#define SM_CNI   16384                   // 128 f32
#define SM_PI    16896
#define SM_CNJ   17408
#define SM_PJ    17920
#define SM_T     18432                   // 128x128 f32 = 64KB
#define SMEM_BYTES (18432 + 65536)       // 83968

__device__ __forceinline__ float ex2f(float x)
{ float y; asm("ex2.approx.ftz.f32 %0, %1;" : "=f"(y) : "f"(x)); return y; }
__device__ __forceinline__ float lg2f(float x)
{ float y; asm("lg2.approx.ftz.f32 %0, %1;" : "=f"(y) : "f"(x)); return y; }

// 16B-unit index into the 128x128-float staging buffer T.
// Write phase: rl = tx*8+jj -> (rl>>2)&31 = (tx*2 + (jj>>2)) distinct across
// lanes -> xor'd unit-columns all distinct -> conflict-free STS.128.
// Read phase: fixed rl, c4 = lane -> xor is a permutation -> conflict-free.
__device__ __forceinline__ int tsw(int rl, int c4)
{
    return rl * 32 + (c4 ^ ((rl >> 2) & 31));
}

// ---------------------------------------------------------------------------
// One 128x128 (i,j) tile per block, triangular tiles only (it <= jt).
// 256 threads, 8x8 micro-tile. Off-diagonal tiles write the transposed block
// through a full-tile smem staging buffer with a single sync (w computed once).
// ---------------------------------------------------------------------------
__global__ __launch_bounds__(256, 2)
void qcd_main_kernel(const float* __restrict__ emb,
                     const float* __restrict__ alpha_p,
                     const float* __restrict__ beta_p,
                     float* __restrict__ out)
{
    extern __shared__ __align__(16) unsigned char smraw[];
    float (*As)[TILE] = reinterpret_cast<float(*)[TILE]>(smraw + SM_AS);
    float (*Bs)[TILE] = reinterpret_cast<float(*)[TILE]>(smraw + SM_BS);
    float* cni_s = reinterpret_cast<float*>(smraw + SM_CNI);
    float* pi_s  = reinterpret_cast<float*>(smraw + SM_PI);
    float* cnj_s = reinterpret_cast<float*>(smraw + SM_CNJ);
    float* pj_s  = reinterpret_cast<float*>(smraw + SM_PJ);
    float4* Tq   = reinterpret_cast<float4*>(smraw + SM_T);

    // Tile index: off-diagonal pairs first (it<jt), diagonal tiles in the tail.
    const int t = blockIdx.x;
    int it, jt;
    if (t < NOFF) {
        jt = (int)((1.0f + sqrtf(8.0f * (float)t + 1.0f)) * 0.5f);
        if (jt * (jt - 1) / 2 > t)        jt--;
        else if ((jt + 1) * jt / 2 <= t)  jt++;
        it = t - jt * (jt - 1) / 2;
    } else {
        it = jt = t - NOFF;
    }

    const int b  = blockIdx.y;
    const int i0 = it * TILE;
    const int j0 = jt * TILE;
    const int tid = threadIdx.x;

    const float* eb = emb + (size_t)b * FDIM * NPTS;

    // Tile loads: 2x (16 rows x 32 float4) over 256 threads.
#pragma unroll
    for (int k = 0; k < 2; ++k) {
        int q  = tid + k * 256;
        int f  = q >> 5;
        int n4 = q & 31;
        *(float4*)&As[f][n4 * 4] = *(const float4*)&eb[f * NPTS + i0 + n4 * 4];
        *(float4*)&Bs[f][n4 * 4] = *(const float4*)&eb[f * NPTS + j0 + n4 * 4];
    }
    __syncthreads();

    // Norms (pre-scaled by c = -beta^2*log2e) and m^(2*alpha)
    const float alpha2 = 2.0f * alpha_p[0];
    const float beta   = beta_p[0];
    const float cl     = -(beta * beta) * 1.4426950408889634f;
    const float m2cl   = -2.0f * cl;
    if (tid < 128) {
        float s = 0.0f;
#pragma unroll
        for (int f = 0; f < FDIM; ++f) { float v = As[f][tid]; s = fmaf(v, v, s); }
        cni_s[tid] = cl * s;
        pi_s[tid]  = ex2f(alpha2 * lg2f(As[4][tid]));
    } else {
        int tt = tid - 128;
        float s = 0.0f;
#pragma unroll
        for (int f = 0; f < FDIM; ++f) { float v = Bs[f][tt]; s = fmaf(v, v, s); }
        cnj_s[tt] = cl * s;
        pj_s[tt]  = ex2f(alpha2 * lg2f(Bs[4][tt]));
    }
    __syncthreads();

    const int tx = tid & 15;   // j sub-tile: cols tx*8 .. +7
    const int ty = tid >> 4;   // i sub-tile: rows ty*8 .. +7

    float acc[8][8];
#pragma unroll
    for (int ii = 0; ii < 8; ++ii)
#pragma unroll
        for (int jj = 0; jj < 8; ++jj) acc[ii][jj] = 0.0f;

    // Scalar mainloop: 4 LDS.128 + 64 FFMA per f-step.
#pragma unroll
    for (int f = 0; f < FDIM; ++f) {
        float4 a0 = *(const float4*)&As[f][ty * 8];
        float4 a1 = *(const float4*)&As[f][ty * 8 + 4];
        float4 b0 = *(const float4*)&Bs[f][tx * 8];
        float4 b1 = *(const float4*)&Bs[f][tx * 8 + 4];
        float av[8] = {a0.x, a0.y, a0.z, a0.w, a1.x, a1.y, a1.z, a1.w};
        float bv[8] = {b0.x, b0.y, b0.z, b0.w, b1.x, b1.y, b1.z, b1.w};
#pragma unroll
        for (int ii = 0; ii < 8; ++ii)
#pragma unroll
            for (int jj = 0; jj < 8; ++jj)
                acc[ii][jj] = fmaf(av[ii], bv[jj], acc[ii][jj]);
    }

    float cni[8], pi[8], cnj[8], pj[8];
#pragma unroll
    for (int k = 0; k < 8; ++k) {
        cni[k] = cni_s[ty * 8 + k];
        pi[k]  = pi_s [ty * 8 + k];
        cnj[k] = cnj_s[tx * 8 + k];
        pj[k]  = pj_s [tx * 8 + k];
    }

    // Compute w once, in place over acc.
#pragma unroll
    for (int ii = 0; ii < 8; ++ii)
#pragma unroll
        for (int jj = 0; jj < 8; ++jj) {
            float x = fmaf(m2cl, acc[ii][jj], cni[ii] + cnj[jj]);
            acc[ii][jj] = ex2f(fminf(pi[ii], pj[jj]) * x);
        }

    // Direct (i,j) block store (row-major over w rows).
    float* orow = out + (size_t)b * NPTS * NPTS + (size_t)(i0 + ty * 8) * NPTS + j0 + tx * 8;
#pragma unroll
    for (int ii = 0; ii < 8; ++ii) {
        float4* dst = (float4*)(orow + (size_t)ii * NPTS);
        dst[0] = make_float4(acc[ii][0], acc[ii][1], acc[ii][2], acc[ii][3]);
        dst[1] = make_float4(acc[ii][4], acc[ii][5], acc[ii][6], acc[ii][7]);
    }

    // Mirror (j,i) block: transpose through T, single sync, coalesced stores.
    if (it != jt) {
#pragma unroll
        for (int jj = 0; jj < 8; ++jj) {
            int rl = tx * 8 + jj;                // T row = local j
            Tq[tsw(rl, 2 * ty + 0)] =
                make_float4(acc[0][jj], acc[1][jj], acc[2][jj], acc[3][jj]);
            Tq[tsw(rl, 2 * ty + 1)] =
                make_float4(acc[4][jj], acc[5][jj], acc[6][jj], acc[7][jj]);
        }
        __syncthreads();
        // Readback: 128 rows x 32 float4 = 4096 float4, 16 per thread.
#pragma unroll
        for (int k = 0; k < 16; ++k) {
            int idx = tid + k * 256;
            int rl  = idx >> 5;
            int c4  = idx & 31;
            float* mrow = out + (size_t)b * NPTS * NPTS + (size_t)(j0 + rl) * NPTS + i0;
            *(float4*)(mrow + c4 * 4) = Tq[tsw(rl, c4)];
        }
    }
}

// ---------------------------------------------------------------------------
extern "C" void kernel_launch(void* const* d_in, const int* in_sizes, int n_in,
                              void* d_out, int out_size)
{
    const float* emb     = (const float*)d_in[0];
    const float* alpha_p = (const float*)d_in[1];
    const float* beta_p  = (const float*)d_in[2];
    float* out = (float*)d_out;

    static int configured = 0;
    cudaFuncSetAttribute(qcd_main_kernel,
                         cudaFuncAttributeMaxDynamicSharedMemorySize, SMEM_BYTES);
    (void)configured;

    dim3 grid(NTRI, BATCH);   // 136 x 8 = 1088 CTAs
    qcd_main_kernel<<<grid, 256, SMEM_BYTES>>>(emb, alpha_p, beta_p, out);
}